// round 11
// baseline (speedup 1.0000x reference)
#include <cuda_runtime.h>
#include <cstdint>

// ---------------------------------------------------------------------------
// Loss_54494545052046, R11 = R6 champion verbatim (R10 had a transcription
// typo in the never-taken tail path; fixed). A/B re-baseline after the
// anomalous R8 measurement bracketed by R7/R9 infra failures.
//   loss = mean|p - t| + 0.1 * mean((dir(p) - dir(t))^2)
//   - FRAMES=16, double-buffered cp.async, 5 CTAs/SM, persistent grid
//   - bone phase: 16 half-warp chain roles x 4 bones, endpoint reuse,
//     fully uniform (dummy chains emit exact 0 via lp>0 guard)
//   - deterministic last-block finalize
// ---------------------------------------------------------------------------

#define NT      256
#define FRAMES  16
#define TILE_F  2400          // floats per array per tile
#define TILE_F4 600
#define MAXB    1024

__device__ double       g_pa[MAXB];
__device__ double       g_pb[MAXB];
__device__ unsigned int g_count = 0;

// 16 chain roles x 5 joints, premultiplied by 3 (float offsets).
// roles 0-4: hand1 fingers, 5-9: hand2 fingers, 10-11: body chains,
// 12: (4,29)+dummies, 13: (0,2)+dummies, 14-15: all dummy.
__constant__ int c_chain[16][5] = {
    {24,27,30,33,36}, {24,39,42,45,48}, {24,51,54,57,60}, {24,63,66,69,72},
    {24,75,78,81,84}, {87,90,93,96,99}, {87,102,105,108,111},
    {87,114,117,120,123}, {87,126,129,132,135}, {87,138,141,144,147},
    {0,3,6,9,12}, {3,15,18,21,24},
    {12,87,87,87,87}, {0,6,6,6,6}, {0,0,0,0,0}, {0,0,0,0,0}
};

__device__ __forceinline__ uint32_t smem_u32(const void* p) {
    uint32_t a;
    asm("{ .reg .u64 t; cvta.to.shared.u64 t, %1; cvt.u32.u64 %0, t; }"
        : "=r"(a) : "l"(p));
    return a;
}
__device__ __forceinline__ void cpa16(uint32_t dst, const float* src) {
    asm volatile("cp.async.cg.shared.global [%0], [%1], 16;"
                 :: "r"(dst), "l"(src) : "memory");
}
__device__ __forceinline__ void cpa_commit() {
    asm volatile("cp.async.commit_group;" ::: "memory");
}
template <int N>
__device__ __forceinline__ void cpa_wait() {
    asm volatile("cp.async.wait_group %0;" :: "n"(N) : "memory");
}

__global__ __launch_bounds__(NT, 5)
void loss_kernel(const float* __restrict__ preds,
                 const float* __restrict__ targets,
                 float* __restrict__ out,
                 int n_frames, int n_tiles, double invN)
{
    __shared__ float  s_p[2][TILE_F];
    __shared__ float  s_t[2][TILE_F];
    __shared__ double s_ra[NT / 32];
    __shared__ double s_rb[NT / 32];
    __shared__ int    s_last;

    const int tid   = threadIdx.x;
    const int lane  = tid & 31;
    const int wid   = tid >> 5;
    const int frame = lane & 15;
    const int role  = (wid << 1) | (lane >> 4);

    const uint32_t sp32 = smem_u32(s_p);
    const uint32_t st32 = smem_u32(s_t);

    // preload this thread's chain (5 joint float-offsets)
    int ch[5];
    #pragma unroll
    for (int s = 0; s < 5; s++) ch[s] = c_chain[role][s];

    float l1 = 0.f, mse = 0.f;

    const int L = (n_tiles > blockIdx.x)
                ? (n_tiles - blockIdx.x + gridDim.x - 1) / gridDim.x : 0;

    const long long step = (long long)gridDim.x * TILE_F;
    // staging pointers for the NEXT tile to stage (advance by step per call)
    const float* gp_next = preds   + (long long)blockIdx.x * TILE_F + 4 * tid;
    const float* gt_next = targets + (long long)blockIdx.x * TILE_F + 4 * tid;
    int stage_k = blockIdx.x;     // global tile index of next stage

    // stage one tile into buffer (stage_j & 1); ALWAYS commits one group
    auto stage = [&](int j) {
        if (stage_k < n_tiles &&
            min(FRAMES, n_frames - stage_k * FRAMES) == FRAMES) {
            const uint32_t boff = (uint32_t)(j & 1) * (TILE_F * 4);
            const uint32_t dp = sp32 + boff + 16u * tid;
            const uint32_t dt = st32 + boff + 16u * tid;
            cpa16(dp,          gp_next);
            cpa16(dt,          gt_next);
            cpa16(dp + 4096u,  gp_next + 1024);
            cpa16(dt + 4096u,  gt_next + 1024);
            if (tid < TILE_F4 - 512) {
                cpa16(dp + 8192u, gp_next + 2048);
                cpa16(dt + 8192u, gt_next + 2048);
            }
        }
        cpa_commit();
        gp_next += step;
        gt_next += step;
        stage_k += gridDim.x;
    };

    stage(0);
    stage(1);

    for (int j = 0; j < L; j++) {
        const int b     = j & 1;
        const int k     = blockIdx.x + j * gridDim.x;
        const int valid = min(FRAMES, n_frames - k * FRAMES);

        cpa_wait<1>();            // tile j's group retired

        if (valid == FRAMES) {
            // ---- L1 on own-copied slots (pre-barrier: own data visible) ----
            {
                const float4* p4 = (const float4*)&s_p[b][4 * tid];
                const float4* t4 = (const float4*)&s_t[b][4 * tid];
                float4 p = p4[0],   t = t4[0];
                l1 += fabsf(p.x - t.x) + fabsf(p.y - t.y)
                    + fabsf(p.z - t.z) + fabsf(p.w - t.w);
                p = p4[256]; t = t4[256];
                l1 += fabsf(p.x - t.x) + fabsf(p.y - t.y)
                    + fabsf(p.z - t.z) + fabsf(p.w - t.w);
                if (tid < TILE_F4 - 512) {
                    p = p4[512]; t = t4[512];
                    l1 += fabsf(p.x - t.x) + fabsf(p.y - t.y)
                        + fabsf(p.z - t.z) + fabsf(p.w - t.w);
                }
            }
            __syncthreads();      // publish tile to all threads

            // ---- bone phase: uniform chain walk, 4 bones, endpoint reuse --
            const float* pp = &s_p[b][frame * 150];
            const float* tp = &s_t[b][frame * 150];
            float pax = pp[ch[0]], pay = pp[ch[0]+1], paz = pp[ch[0]+2];
            float tax = tp[ch[0]], tay = tp[ch[0]+1], taz = tp[ch[0]+2];
            #pragma unroll
            for (int s = 1; s < 5; s++) {
                const int jb = ch[s];
                const float pbx = pp[jb], pby = pp[jb+1], pbz = pp[jb+2];
                const float tbx = tp[jb], tby = tp[jb+1], tbz = tp[jb+2];
                const float dpx = pax - pbx, dpy = pay - pby, dpz = paz - pbz;
                const float dtx = tax - tbx, dty = tay - tby, dtz = taz - tbz;
                const float lp = dpx*dpx + dpy*dpy + dpz*dpz;
                const float lt = dtx*dtx + dty*dty + dtz*dtz;
                const float ip = (lp > 0.f) ? rsqrtf(lp) : 0.f;
                const float it = (lt > 0.f) ? rsqrtf(lt) : 0.f;
                const float dx = dpx*ip - dtx*it;
                const float dy = dpy*ip - dty*it;
                const float dz = dpz*ip - dtz*it;
                mse += dx*dx + dy*dy + dz*dz;
                pax = pbx; pay = pby; paz = pbz;
                tax = tbx; tay = tby; taz = tbz;
            }
            __syncthreads();      // buffer b free for tile j+2
        } else {
            // tail (never taken for 64x4096): direct-global uniform chains
            const long long base = (long long)k * TILE_F;
            const int nfl = valid * 150;
            for (int i = tid; i < nfl; i += NT) {
                l1 += fabsf(preds[base + i] - targets[base + i]);
            }
            for (int idx = tid; idx < valid * 16; idx += NT) {
                const int f = idx >> 4;
                const int r = idx & 15;
                const float* ppg = preds   + base + (long long)f * 150;
                const float* tpg = targets + base + (long long)f * 150;
                int j0 = c_chain[r][0];
                float pax2 = ppg[j0], pay2 = ppg[j0+1], paz2 = ppg[j0+2];
                float tax2 = tpg[j0], tay2 = tpg[j0+1], taz2 = tpg[j0+2];
                #pragma unroll
                for (int s = 1; s < 5; s++) {
                    const int jb = c_chain[r][s];
                    const float pbx = ppg[jb], pby = ppg[jb+1], pbz = ppg[jb+2];
                    const float tbx = tpg[jb], tby = tpg[jb+1], tbz = tpg[jb+2];
                    const float dpx = pax2 - pbx, dpy = pay2 - pby, dpz = paz2 - pbz;
                    const float dtx = tax2 - tbx, dty = tay2 - tby, dtz = taz2 - tbz;
                    const float lp = dpx*dpx + dpy*dpy + dpz*dpz;
                    const float lt = dtx*dtx + dty*dty + dtz*dtz;
                    const float ipv = (lp > 0.f) ? rsqrtf(lp) : 0.f;
                    const float itv = (lt > 0.f) ? rsqrtf(lt) : 0.f;
                    const float dx = dpx*ipv - dtx*itv;
                    const float dy = dpy*ipv - dty*itv;
                    const float dz = dpz*ipv - dtz*itv;
                    mse += dx*dx + dy*dy + dz*dz;
                    pax2 = pbx; pay2 = pby; paz2 = pbz;
                    tax2 = tbx; tay2 = tby; taz2 = tbz;
                }
            }
            __syncthreads();
            __syncthreads();
        }

        stage(j + 2);             // refill buffer b (empty commit if OOR)
    }

    // ---- deterministic block reduction ----
    double a  = (double)l1;
    double bb = (double)mse;
    #pragma unroll
    for (int off = 16; off > 0; off >>= 1) {
        a  += __shfl_down_sync(0xffffffffu, a,  off);
        bb += __shfl_down_sync(0xffffffffu, bb, off);
    }
    if (lane == 0) { s_ra[wid] = a; s_rb[wid] = bb; }
    __syncthreads();
    if (wid == 0) {
        a  = (lane < NT / 32) ? s_ra[lane] : 0.0;
        bb = (lane < NT / 32) ? s_rb[lane] : 0.0;
        #pragma unroll
        for (int off = 4; off > 0; off >>= 1) {
            a  += __shfl_down_sync(0xffffffffu, a,  off);
            bb += __shfl_down_sync(0xffffffffu, bb, off);
        }
    }
    if (tid == 0) {
        g_pa[blockIdx.x] = a;
        g_pb[blockIdx.x] = bb;
        __threadfence();
        const unsigned int old = atomicAdd(&g_count, 1u);
        s_last = (old == gridDim.x - 1) ? 1 : 0;
    }
    __syncthreads();

    if (s_last) {
        double fa = 0.0, fb = 0.0;
        for (int i = tid; i < gridDim.x; i += NT) {
            fa += __ldcg(&g_pa[i]);
            fb += __ldcg(&g_pb[i]);
        }
        #pragma unroll
        for (int off = 16; off > 0; off >>= 1) {
            fa += __shfl_down_sync(0xffffffffu, fa, off);
            fb += __shfl_down_sync(0xffffffffu, fb, off);
        }
        if (lane == 0) { s_ra[wid] = fa; s_rb[wid] = fb; }
        __syncthreads();
        if (tid == 0) {
            fa = 0.0; fb = 0.0;
            #pragma unroll
            for (int w = 0; w < NT / 32; w++) { fa += s_ra[w]; fb += s_rb[w]; }
            out[0] = (float)((fa + 0.1 * fb) * invN);
            g_count = 0;   // reset for next graph replay
        }
    }
}

extern "C" void kernel_launch(void* const* d_in, const int* in_sizes, int n_in,
                              void* d_out, int out_size)
{
    const float* preds   = (const float*)d_in[0];
    const float* targets = (const float*)d_in[1];
    float* out = (float*)d_out;

    const int n        = in_sizes[0];                    // B*T*150
    const int n_frames = n / 150;
    const int n_tiles  = (n_frames + FRAMES - 1) / FRAMES;

    int grid = 148 * 5;                                  // 5 CTAs/SM
    if (grid > n_tiles) grid = n_tiles;
    if (grid > MAXB)    grid = MAXB;

    loss_kernel<<<grid, NT>>>(preds, targets, out, n_frames, n_tiles,
                              1.0 / (double)n);
}

// round 12
// speedup vs baseline: 1.4994x; 1.4994x over previous
#include <cuda_runtime.h>
#include <cstdint>

// ---------------------------------------------------------------------------
// Loss_54494545052046, R12 = guard-free-norm variant (R7), re-submitted now
// that R11's A/B proved the environment (not the code) caused R8's 84us:
// identical R6 source measured 58.3us (R6) vs 86.8us (R11). Like-for-like on
// the degraded node, guard-free (84.1) beat guarded (86.8).
//   loss = mean|p - t| + 0.1 * mean((dir(p) - dir(t))^2)
//   - norm guard folded into fma: ip = rsqrt(dot(d,d) + 1e-30)
//     * real bones: +1e-30 below fp32 rounding
//     * dummy bones (ja==jb): d=0 -> ip finite -> contribution exactly 0
//   - FRAMES=16, double-buffered cp.async, 5 CTAs/SM, persistent grid
//   - 16 uniform half-warp chain roles, endpoint reuse
//   - deterministic last-block finalize
// ---------------------------------------------------------------------------

#define NT      256
#define FRAMES  16
#define TILE_F  2400          // floats per array per tile
#define TILE_F4 600
#define MAXB    1024

__device__ double       g_pa[MAXB];
__device__ double       g_pb[MAXB];
__device__ unsigned int g_count = 0;

// 16 chain roles x 5 joints, premultiplied by 3 (float offsets).
__constant__ int c_chain[16][5] = {
    {24,27,30,33,36}, {24,39,42,45,48}, {24,51,54,57,60}, {24,63,66,69,72},
    {24,75,78,81,84}, {87,90,93,96,99}, {87,102,105,108,111},
    {87,114,117,120,123}, {87,126,129,132,135}, {87,138,141,144,147},
    {0,3,6,9,12}, {3,15,18,21,24},
    {12,87,87,87,87}, {0,6,6,6,6}, {0,0,0,0,0}, {0,0,0,0,0}
};

__device__ __forceinline__ uint32_t smem_u32(const void* p) {
    uint32_t a;
    asm("{ .reg .u64 t; cvta.to.shared.u64 t, %1; cvt.u32.u64 %0, t; }"
        : "=r"(a) : "l"(p));
    return a;
}
__device__ __forceinline__ void cpa16(uint32_t dst, const float* src) {
    asm volatile("cp.async.cg.shared.global [%0], [%1], 16;"
                 :: "r"(dst), "l"(src) : "memory");
}
__device__ __forceinline__ void cpa_commit() {
    asm volatile("cp.async.commit_group;" ::: "memory");
}
template <int N>
__device__ __forceinline__ void cpa_wait() {
    asm volatile("cp.async.wait_group %0;" :: "n"(N) : "memory");
}

// guard-free bone update: dummy bones (all diffs 0) contribute exactly 0
__device__ __forceinline__ void bone(
    float pax, float pay, float paz, float tax, float tay, float taz,
    float pbx, float pby, float pbz, float tbx, float tby, float tbz,
    float& mse)
{
    const float dpx = pax - pbx, dpy = pay - pby, dpz = paz - pbz;
    const float dtx = tax - tbx, dty = tay - tby, dtz = taz - tbz;
    const float lp = fmaf(dpx, dpx, fmaf(dpy, dpy, fmaf(dpz, dpz, 1e-30f)));
    const float lt = fmaf(dtx, dtx, fmaf(dty, dty, fmaf(dtz, dtz, 1e-30f)));
    const float ip = rsqrtf(lp);
    const float it = rsqrtf(lt);
    const float dx = dpx * ip - dtx * it;
    const float dy = dpy * ip - dty * it;
    const float dz = dpz * ip - dtz * it;
    mse = fmaf(dx, dx, fmaf(dy, dy, fmaf(dz, dz, mse)));
}

__global__ __launch_bounds__(NT, 5)
void loss_kernel(const float* __restrict__ preds,
                 const float* __restrict__ targets,
                 float* __restrict__ out,
                 int n_frames, int n_tiles, double invN)
{
    __shared__ float  s_p[2][TILE_F];
    __shared__ float  s_t[2][TILE_F];
    __shared__ double s_ra[NT / 32];
    __shared__ double s_rb[NT / 32];
    __shared__ int    s_last;

    const int tid   = threadIdx.x;
    const int lane  = tid & 31;
    const int wid   = tid >> 5;
    const int frame = lane & 15;
    const int role  = (wid << 1) | (lane >> 4);

    const uint32_t sp32 = smem_u32(s_p);
    const uint32_t st32 = smem_u32(s_t);

    // preload this thread's chain (5 joint float-offsets)
    int ch[5];
    #pragma unroll
    for (int s = 0; s < 5; s++) ch[s] = c_chain[role][s];

    float l1 = 0.f, mse = 0.f;

    const int L = (n_tiles > blockIdx.x)
                ? (n_tiles - blockIdx.x + gridDim.x - 1) / gridDim.x : 0;

    const long long step = (long long)gridDim.x * TILE_F;
    const float* gp_next = preds   + (long long)blockIdx.x * TILE_F + 4 * tid;
    const float* gt_next = targets + (long long)blockIdx.x * TILE_F + 4 * tid;
    int stage_k = blockIdx.x;

    // stage one tile into buffer (j & 1); ALWAYS commits exactly one group
    auto stage = [&](int j) {
        if (stage_k < n_tiles &&
            min(FRAMES, n_frames - stage_k * FRAMES) == FRAMES) {
            const uint32_t boff = (uint32_t)(j & 1) * (TILE_F * 4);
            const uint32_t dp = sp32 + boff + 16u * tid;
            const uint32_t dt = st32 + boff + 16u * tid;
            cpa16(dp,          gp_next);
            cpa16(dt,          gt_next);
            cpa16(dp + 4096u,  gp_next + 1024);
            cpa16(dt + 4096u,  gt_next + 1024);
            if (tid < TILE_F4 - 512) {
                cpa16(dp + 8192u, gp_next + 2048);
                cpa16(dt + 8192u, gt_next + 2048);
            }
        }
        cpa_commit();
        gp_next += step;
        gt_next += step;
        stage_k += gridDim.x;
    };

    stage(0);
    stage(1);

    for (int j = 0; j < L; j++) {
        const int b     = j & 1;
        const int k     = blockIdx.x + j * gridDim.x;
        const int valid = min(FRAMES, n_frames - k * FRAMES);

        cpa_wait<1>();            // tile j's group retired

        if (valid == FRAMES) {
            // ---- L1 on own-copied slots (own data visible post-wait) ----
            {
                const float4* p4 = (const float4*)&s_p[b][4 * tid];
                const float4* t4 = (const float4*)&s_t[b][4 * tid];
                float4 p = p4[0],   t = t4[0];
                l1 += fabsf(p.x - t.x) + fabsf(p.y - t.y)
                    + fabsf(p.z - t.z) + fabsf(p.w - t.w);
                p = p4[256]; t = t4[256];
                l1 += fabsf(p.x - t.x) + fabsf(p.y - t.y)
                    + fabsf(p.z - t.z) + fabsf(p.w - t.w);
                if (tid < TILE_F4 - 512) {
                    p = p4[512]; t = t4[512];
                    l1 += fabsf(p.x - t.x) + fabsf(p.y - t.y)
                        + fabsf(p.z - t.z) + fabsf(p.w - t.w);
                }
            }
            __syncthreads();      // publish tile to all threads

            // ---- bone phase: uniform chain walk, 4 bones, endpoint reuse --
            const float* pp = &s_p[b][frame * 150];
            const float* tp = &s_t[b][frame * 150];
            float pax = pp[ch[0]], pay = pp[ch[0]+1], paz = pp[ch[0]+2];
            float tax = tp[ch[0]], tay = tp[ch[0]+1], taz = tp[ch[0]+2];
            #pragma unroll
            for (int s = 1; s < 5; s++) {
                const int jb = ch[s];
                const float pbx = pp[jb], pby = pp[jb+1], pbz = pp[jb+2];
                const float tbx = tp[jb], tby = tp[jb+1], tbz = tp[jb+2];
                bone(pax, pay, paz, tax, tay, taz,
                     pbx, pby, pbz, tbx, tby, tbz, mse);
                pax = pbx; pay = pby; paz = pbz;
                tax = tbx; tay = tby; taz = tbz;
            }
            __syncthreads();      // buffer b free for tile j+2
        } else {
            // tail (never taken for 64x4096): direct-global uniform chains
            const long long base = (long long)k * TILE_F;
            const int nfl = valid * 150;
            for (int i = tid; i < nfl; i += NT) {
                l1 += fabsf(preds[base + i] - targets[base + i]);
            }
            for (int idx = tid; idx < valid * 16; idx += NT) {
                const int f = idx >> 4;
                const int r = idx & 15;
                const float* ppg = preds   + base + (long long)f * 150;
                const float* tpg = targets + base + (long long)f * 150;
                int j0 = c_chain[r][0];
                float pax2 = ppg[j0], pay2 = ppg[j0+1], paz2 = ppg[j0+2];
                float tax2 = tpg[j0], tay2 = tpg[j0+1], taz2 = tpg[j0+2];
                #pragma unroll
                for (int s = 1; s < 5; s++) {
                    const int jb = c_chain[r][s];
                    const float pbx = ppg[jb], pby = ppg[jb+1], pbz = ppg[jb+2];
                    const float tbx = tpg[jb], tby = tpg[jb+1], tbz = tpg[jb+2];
                    bone(pax2, pay2, paz2, tax2, tay2, taz2,
                         pbx, pby, pbz, tbx, tby, tbz, mse);
                    pax2 = pbx; pay2 = pby; paz2 = pbz;
                    tax2 = tbx; tay2 = tby; taz2 = tbz;
                }
            }
            __syncthreads();
            __syncthreads();
        }

        stage(j + 2);             // refill buffer b (empty commit if OOR)
    }

    // ---- deterministic block reduction ----
    double a  = (double)l1;
    double bb = (double)mse;
    #pragma unroll
    for (int off = 16; off > 0; off >>= 1) {
        a  += __shfl_down_sync(0xffffffffu, a,  off);
        bb += __shfl_down_sync(0xffffffffu, bb, off);
    }
    if (lane == 0) { s_ra[wid] = a; s_rb[wid] = bb; }
    __syncthreads();
    if (wid == 0) {
        a  = (lane < NT / 32) ? s_ra[lane] : 0.0;
        bb = (lane < NT / 32) ? s_rb[lane] : 0.0;
        #pragma unroll
        for (int off = 4; off > 0; off >>= 1) {
            a  += __shfl_down_sync(0xffffffffu, a,  off);
            bb += __shfl_down_sync(0xffffffffu, bb, off);
        }
    }
    if (tid == 0) {
        g_pa[blockIdx.x] = a;
        g_pb[blockIdx.x] = bb;
        __threadfence();
        const unsigned int old = atomicAdd(&g_count, 1u);
        s_last = (old == gridDim.x - 1) ? 1 : 0;
    }
    __syncthreads();

    if (s_last) {
        double fa = 0.0, fb = 0.0;
        for (int i = tid; i < gridDim.x; i += NT) {
            fa += __ldcg(&g_pa[i]);
            fb += __ldcg(&g_pb[i]);
        }
        #pragma unroll
        for (int off = 16; off > 0; off >>= 1) {
            fa += __shfl_down_sync(0xffffffffu, fa, off);
            fb += __shfl_down_sync(0xffffffffu, fb, off);
        }
        if (lane == 0) { s_ra[wid] = fa; s_rb[wid] = fb; }
        __syncthreads();
        if (tid == 0) {
            fa = 0.0; fb = 0.0;
            #pragma unroll
            for (int w = 0; w < NT / 32; w++) { fa += s_ra[w]; fb += s_rb[w]; }
            out[0] = (float)((fa + 0.1 * fb) * invN);
            g_count = 0;   // reset for next graph replay
        }
    }
}

extern "C" void kernel_launch(void* const* d_in, const int* in_sizes, int n_in,
                              void* d_out, int out_size)
{
    const float* preds   = (const float*)d_in[0];
    const float* targets = (const float*)d_in[1];
    float* out = (float*)d_out;

    const int n        = in_sizes[0];                    // B*T*150
    const int n_frames = n / 150;
    const int n_tiles  = (n_frames + FRAMES - 1) / FRAMES;

    int grid = 148 * 5;                                  // 5 CTAs/SM
    if (grid > n_tiles) grid = n_tiles;
    if (grid > MAXB)    grid = MAXB;

    loss_kernel<<<grid, NT>>>(preds, targets, out, n_frames, n_tiles,
                              1.0 / (double)n);
}